// round 16
// baseline (speedup 1.0000x reference)
#include <cuda_runtime.h>
#include <cuda_fp16.h>
#include <cstdint>

#define N_TOK   16384
#define DIM     1024
#define NEXP    64
#define CAP     640

#define BM 128
#define BN 128
#define KC 32
#define NK (DIM / KC)                 // 32 K-chunks
#define A_STG 10240                   // 128 rows * 80 B
#define RS    272                     // B smem row stride: 256 B data + 16 pad
#define B_STG (32 * RS)               // 8704
#define STG   (A_STG + B_STG)         // 18944
#define SMEM_BYTES (4 * STG)          // 75776, 4 stages

#define TILES 128
#define TSZ   256

// ---------------- persistent scratch ------------------------------------------
__device__ int   g_ef[2 * N_TOK];
__device__ float g_gf[2 * N_TOK];
__device__ int   g_slot_tok[NEXP * CAP];
__device__ float g_slot_gate[NEXP * CAP];
__device__ int   g_cnt[NEXP];
__device__ int   g_tile_base[TILES * NEXP];
__device__ int   g_tile_hist[TILES * NEXP];   // statically zero; scanB re-zeroes
__device__ __align__(1024) __half g_xh[(size_t)N_TOK * DIM];  // fp16 x, token-indexed

// ---------------- helpers -----------------------------------------------------
__device__ __forceinline__ uint32_t smem_u32(const void* p) {
    uint32_t a;
    asm("{ .reg .u64 t; cvta.to.shared.u64 t, %1; cvt.u32.u64 %0, t; }"
        : "=r"(a) : "l"(p));
    return a;
}
__device__ __forceinline__ void cp16(uint32_t s, const void* g) {
    asm volatile("cp.async.cg.shared.global [%0], [%1], 16;" :: "r"(s), "l"(g));
}
#define CP_COMMIT() asm volatile("cp.async.commit_group;" ::: "memory")

__device__ __forceinline__ void ldsm_x4(uint32_t* r, uint32_t addr) {
    asm volatile("ldmatrix.sync.aligned.m8n8.x4.shared.b16 {%0,%1,%2,%3}, [%4];"
                 : "=r"(r[0]), "=r"(r[1]), "=r"(r[2]), "=r"(r[3]) : "r"(addr));
}
__device__ __forceinline__ void ldsm_x2_trans(uint32_t* r, uint32_t addr) {
    asm volatile("ldmatrix.sync.aligned.m8n8.x2.trans.shared.b16 {%0,%1}, [%2];"
                 : "=r"(r[0]), "=r"(r[1]) : "r"(addr));
}
__device__ __forceinline__ void mma16816(float* c, const uint32_t* a,
                                         const uint32_t* b) {
    asm volatile(
        "mma.sync.aligned.m16n8k16.row.col.f32.f16.f16.f32 "
        "{%0,%1,%2,%3}, {%4,%5,%6,%7}, {%8,%9}, {%0,%1,%2,%3};"
        : "+f"(c[0]), "+f"(c[1]), "+f"(c[2]), "+f"(c[3])
        : "r"(a[0]), "r"(a[1]), "r"(a[2]), "r"(a[3]), "r"(b[0]), "r"(b[1]));
}

// ---------------- K1: FAT prelude: router(+x->fp16, +tile hist) | zero --------
#define FAT_ROUTER 256
#define FAT_TOTAL  (FAT_ROUTER + 1024)

__global__ void __launch_bounds__(256)
fat_kernel(const float* __restrict__ x,
           const float* __restrict__ Wr,
           const float* __restrict__ br,
           float4* __restrict__ out4) {
    __shared__ float xs[16][64];
    __shared__ float ws[16][64];
    __shared__ float sm[64 * 65];
    const int tid = threadIdx.x;
    const int bx = blockIdx.x;

    if (bx < FAT_ROUTER) {
        const int tx = tid & 15, ty = tid >> 4;
        const int tok0 = bx * 64;
        const int lt = tid >> 2, lq = tid & 3;
        const int wd = tid >> 4, we = (tid & 15) * 4;

        float acc[4][4] = {};
        for (int d0 = 0; d0 < DIM; d0 += 16) {
            float4 xv = *(const float4*)&x[(size_t)(tok0 + lt) * DIM + d0 + lq * 4];
            float4 wv = *(const float4*)&Wr[(size_t)(d0 + wd) * NEXP + we];
            {   // free fp16 conversion of x while it's in registers
                uint2 pk;
                ((__half2*)&pk)[0] = __floats2half2_rn(xv.x, xv.y);
                ((__half2*)&pk)[1] = __floats2half2_rn(xv.z, xv.w);
                *(uint2*)(g_xh + (size_t)(tok0 + lt) * DIM + d0 + lq * 4) = pk;
            }
            __syncthreads();
            xs[lq * 4 + 0][lt] = xv.x; xs[lq * 4 + 1][lt] = xv.y;
            xs[lq * 4 + 2][lt] = xv.z; xs[lq * 4 + 3][lt] = xv.w;
            *(float4*)&ws[wd][we] = wv;
            __syncthreads();
#pragma unroll
            for (int kk = 0; kk < 16; kk++) {
                float a[4], b[4];
#pragma unroll
                for (int i = 0; i < 4; i++) a[i] = xs[kk][ty * 4 + i];
#pragma unroll
                for (int j = 0; j < 4; j++) b[j] = ws[kk][tx * 4 + j];
#pragma unroll
                for (int i = 0; i < 4; i++)
#pragma unroll
                    for (int j = 0; j < 4; j++) acc[i][j] += a[i] * b[j];
            }
        }
        __syncthreads();
#pragma unroll
        for (int i = 0; i < 4; i++)
#pragma unroll
            for (int j = 0; j < 4; j++)
                sm[(ty * 4 + i) * 65 + tx * 4 + j] = acc[i][j] + br[tx * 4 + j];
        __syncthreads();

        if (tid < 64) {
            const int t = tid;
            float v1 = -3.402823466e+38f, v2 = -3.402823466e+38f;
            int i1 = 0, i2 = 0;
#pragma unroll 4
            for (int e = 0; e < NEXP; e++) {
                float v = sm[t * 65 + e];
                if (v > v1) { v2 = v1; i2 = i1; v1 = v; i1 = e; }
                else if (v > v2) { v2 = v; i2 = e; }
            }
            float texp = expf(v2 - v1);
            float inv = 1.f / (1.f + texp);
            int n = tok0 + t;
            g_ef[n]         = i1;
            g_ef[N_TOK + n] = i2;
            g_gf[n]         = inv;
            g_gf[N_TOK + n] = texp * inv;
            // fused scanA: per-tile histograms (hist is zero at launch entry)
            atomicAdd(&g_tile_hist[(n >> 8) * NEXP + i1], 1);
            atomicAdd(&g_tile_hist[((n >> 8) + 64) * NEXP + i2], 1);
        }
    } else {
        const int zb = bx - FAT_ROUTER;
        const int base = zb * 256 + tid;
#pragma unroll
        for (int i = 0; i < 16; i++)
            out4[base + i * 262144] = make_float4(0.f, 0.f, 0.f, 0.f);
    }
}

// ---------------- K2b: per-expert exclusive prefix over tiles (+hist reset) ---
__global__ void __launch_bounds__(1024)
scanB_kernel() {
    const int tid = threadIdx.x;
    const int lane = tid & 31, w = tid >> 5;   // 32 warps
    for (int e = w; e < NEXP; e += 32) {
        int c[4];
#pragma unroll
        for (int j = 0; j < 4; j++)
            c[j] = g_tile_hist[(lane * 4 + j) * NEXP + e];
        int lsum = c[0] + c[1] + c[2] + c[3];
        int v = lsum;
#pragma unroll
        for (int off = 1; off < 32; off <<= 1) {
            int uu = __shfl_up_sync(0xffffffffu, v, off);
            if (lane >= off) v += uu;
        }
        int run = v - lsum;
#pragma unroll
        for (int j = 0; j < 4; j++) {
            g_tile_base[(lane * 4 + j) * NEXP + e] = run;
            run += c[j];
            g_tile_hist[(lane * 4 + j) * NEXP + e] = 0;  // reset for next replay
        }
        if (lane == 31) g_cnt[e] = run;
    }
}

// ---------------- K2c: order-preserving rank + scatter ------------------------
__global__ void __launch_bounds__(TSZ)
scanC_kernel() {
    __shared__ int seg[8 * NEXP];
    const int t = blockIdx.x, tid = threadIdx.x;
    const int lane = tid & 31, w = tid >> 5;

    for (int i = tid; i < 8 * NEXP; i += TSZ) seg[i] = 0;
    __syncthreads();

    const int f = t * TSZ + tid;
    const int e = g_ef[f];
    unsigned m = __match_any_sync(0xffffffffu, e);
    int leader = __ffs(m) - 1;
    int rin = __popc(m & ((1u << lane) - 1u));
    if (lane == leader) seg[w * NEXP + e] = __popc(m);
    __syncthreads();
    if (tid < NEXP) {
        int vals[8];
#pragma unroll
        for (int s = 0; s < 8; s++) vals[s] = seg[s * NEXP + tid];
        int base = 0;
#pragma unroll
        for (int s = 0; s < 8; s++) { seg[s * NEXP + tid] = base; base += vals[s]; }
    }
    __syncthreads();
    const int rank = g_tile_base[t * NEXP + e] + seg[w * NEXP + e] + rin;
    if (rank < CAP) {
        g_slot_tok[e * CAP + rank]  = (f >= N_TOK) ? f - N_TOK : f;
        g_slot_gate[e * CAP + rank] = g_gf[f];
    }
}

// ---------------- K4: GEMM 128x128, 256 thr, 2 CTAs/SM ------------------------
extern __shared__ __align__(128) char dsmem[];

__global__ void __launch_bounds__(256, 2)
moe_mma_kernel(const float* __restrict__ We, float* __restrict__ out) {
    const int e = blockIdx.z;
    const int cnt = min(g_cnt[e], CAP);
    const int m0 = blockIdx.y * BM;
    if (m0 >= cnt) return;
    const int n0 = blockIdx.x * BN;
    const int tid = threadIdx.x;
    const int lane = tid & 31, wid = tid >> 5;
    const int wm = (wid & 1) * 64, wn = (wid >> 1) * 32;

    __shared__ int   tok_s[BM];
    __shared__ float gate_s[BM];
    if (tid < BM) {
        int r = m0 + tid;
        bool v = r < cnt;
        tok_s[tid]  = v ? g_slot_tok[e * CAP + r] : 0;
        gate_s[tid] = v ? g_slot_gate[e * CAP + r] : 0.f;
    }
    __syncthreads();

    const uint32_t sbase = smem_u32(dsmem);

    // ---- A loader (cp.async, gathered): 512 x 16B per stage, 2 per thread ------
    const int ar = tid >> 1, aq = (tid & 1) * 2;   // row 0..127, quad pair
    const __half* Arow = g_xh + (size_t)tok_s[ar] * DIM + aq * 8;
#define CPA(s, kc) do {                                                       \
        cp16(sbase + (s) * STG + ar * 80 + aq * 16, Arow + (kc) * KC);        \
        cp16(sbase + (s) * STG + ar * 80 + aq * 16 + 16,                      \
             Arow + (kc) * KC + 8);                                           \
    } while (0)

    // ---- B loader: lane-major rows (LDG fp32 -> cvt -> STS fp16) ---------------
    // kr = tid&31 (k-row), ng = tid>>5 (col group of 16 floats)
    const int kr = tid & 31, ng = tid >> 5;
    const float* Bld = We + (size_t)e * DIM * DIM + (size_t)kr * DIM + n0 + ng * 16;
    float4 breg[4];
#define LDG_B(kc) do {                                                        \
        const float4* p = (const float4*)(Bld + (size_t)(kc) * KC * DIM);     \
        breg[0] = p[0]; breg[1] = p[1]; breg[2] = p[2]; breg[3] = p[3];       \
    } while (0)
#define STS_B(s) do {                                                         \
        char* sp = dsmem + (s) * STG + A_STG + kr * RS + ng * 32;             \
        uint4 u0, u1;                                                         \
        ((__half2*)&u0)[0] = __floats2half2_rn(breg[0].x, breg[0].y);         \
        ((__half2*)&u0)[1] = __floats2half2_rn(breg[0].z, breg[0].w);         \
        ((__half2*)&u0)[2] = __floats2half2_rn(breg[1].x, breg[1].y);         \
        ((__half2*)&u0)[3] = __floats2half2_rn(breg[1].z, breg[1].w);         \
        ((__half2*)&u1)[0] = __floats2half2_rn(breg[2].x, breg[2].y);         \
        ((__half2*)&u1)[1] = __floats2half2_rn(breg[2].z, breg[2].w);         \
        ((__half2*)&u1)[2] = __floats2half2_rn(breg[3].x, breg[3].y);         \
        ((__half2*)&u1)[3] = __floats2half2_rn(breg[3].z, breg[3].w);         \
        *(uint4*)sp = u0;                                                     \
        *(uint4*)(sp + 16) = u1;                                              \
    } while (0)

    // prologue: A async stages 0..2; B stages 0,1 staged, stage 2 in regs
    CPA(0, 0); CP_COMMIT();
    CPA(1, 1); CP_COMMIT();
    CPA(2, 2); CP_COMMIT();
    LDG_B(0); STS_B(0);
    LDG_B(1); STS_B(1);
    LDG_B(2);

    float acc[4][4][4] = {};

    const uint32_t aoffs = (uint32_t)((wm + (lane & 15)) * 80 + (lane >> 4) * 16);
    const uint32_t btr   = (uint32_t)(A_STG + (lane & 15) * RS + wn * 2);

    for (int kc = 0; kc < NK; kc++) {
        const int buf = kc & 3;
        if (kc + 2 < NK) STS_B((kc + 2) & 3);   // stage written 2 ahead; safe
        if (kc + 3 < NK) LDG_B(kc + 3);
        asm volatile("cp.async.wait_group 2;" ::: "memory");
        __syncthreads();
        if (kc + 3 < NK) CPA((kc + 3) & 3, kc + 3);
        CP_COMMIT();

        const uint32_t sA = sbase + buf * STG;
        const uint32_t sBt = sA + btr;
#pragma unroll
        for (int k16 = 0; k16 < KC; k16 += 16) {
            uint32_t a[4][4], b[4][2];
#pragma unroll
            for (int mi = 0; mi < 4; mi++)
                ldsm_x4(a[mi], sA + aoffs + (uint32_t)(mi * 16 * 80 + k16 * 2));
#pragma unroll
            for (int ni = 0; ni < 4; ni++)
                ldsm_x2_trans(b[ni], sBt + (uint32_t)(k16 * RS + ni * 16));
#pragma unroll
            for (int mi = 0; mi < 4; mi++)
#pragma unroll
                for (int ni = 0; ni < 4; ni++)
                    mma16816(acc[mi][ni], a[mi], b[ni]);
        }
    }

    // fused epilogue: out[token] += gate * relu(acc)
#pragma unroll
    for (int mi = 0; mi < 4; mi++) {
        const int rbase = wm + mi * 16 + (lane >> 2);
#pragma unroll
        for (int h = 0; h < 2; h++) {
            const int rr = rbase + h * 8;
            if (m0 + rr < cnt) {
                const float g = gate_s[rr];
                float* orow = out + (size_t)tok_s[rr] * DIM + n0 + wn +
                              (lane & 3) * 2;
#pragma unroll
                for (int ni = 0; ni < 4; ni++) {
                    float2 v = make_float2(
                        g * fmaxf(acc[mi][ni][2 * h], 0.f),
                        g * fmaxf(acc[mi][ni][2 * h + 1], 0.f));
                    atomicAdd((float2*)(orow + ni * 8), v);
                }
            }
        }
    }
#undef CPA
#undef LDG_B
#undef STS_B
}

// ---------------- launch ------------------------------------------------------
extern "C" void kernel_launch(void* const* d_in, const int* in_sizes, int n_in,
                              void* d_out, int out_size) {
    const float *x = nullptr, *Wr = nullptr, *br = nullptr, *We = nullptr;
    for (int i = 0; i < n_in; i++) {
        switch (in_sizes[i]) {
            case N_TOK * DIM: x  = (const float*)d_in[i]; break;
            case DIM * NEXP:  Wr = (const float*)d_in[i]; break;
            case NEXP:        br = (const float*)d_in[i]; break;
            default:
                if (in_sizes[i] == NEXP * DIM * DIM) We = (const float*)d_in[i];
                break;
        }
    }
    float* out = (float*)d_out;

    cudaFuncSetAttribute(moe_mma_kernel,
                         cudaFuncAttributeMaxDynamicSharedMemorySize, SMEM_BYTES);

    fat_kernel<<<FAT_TOTAL, 256>>>(x, Wr, br, (float4*)out);
    scanB_kernel<<<1, 1024>>>();
    scanC_kernel<<<TILES, TSZ>>>();
    dim3 grid(DIM / BN, (CAP + BM - 1) / BM, NEXP);   // 8 x 5 x 64
    moe_mma_kernel<<<grid, 256, SMEM_BYTES>>>(We, out);
}